// round 11
// baseline (speedup 1.0000x reference)
#include <cuda_runtime.h>
#include <cstdint>

#define N_NODES   100000
#define N_EDGES   1600000
#define HID       128
#define NUM_G     64

// ---------------- scratch (static device globals; no allocation) ----------------
__device__ float g_bufA[(size_t)N_NODES * HID];
__device__ float g_bufB[(size_t)N_NODES * HID];
__device__ float g_wt  [6 * HID * HID];        // transposed weights, k-major
__device__ float g_pool[NUM_G * HID];
__device__ int   g_deg   [N_NODES];
__device__ int   g_rowptr[N_NODES + 1];
__device__ int   g_cursor[N_NODES];
__device__ int   g_csrsrc[N_EDGES];

// ---------------- zero helpers ----------------
__global__ void zero_kernel(float* __restrict__ p, int n4) {
    int i = blockIdx.x * blockDim.x + threadIdx.x;
    if (i < n4) reinterpret_cast<float4*>(p)[i] = make_float4(0.f, 0.f, 0.f, 0.f);
}
__global__ void zero_int_kernel(int* __restrict__ p, int n) {
    int i = blockIdx.x * blockDim.x + threadIdx.x;
    if (i < n) p[i] = 0;
}

// ---------------- CSR build ----------------
__global__ __launch_bounds__(256) void hist_kernel(const int* __restrict__ dst, int* __restrict__ deg) {
    int i = blockIdx.x * blockDim.x + threadIdx.x;
    if (i < N_EDGES) atomicAdd(&deg[dst[i]], 1);
}

__global__ __launch_bounds__(1024) void scan_kernel(const int* __restrict__ deg,
                                                    int* __restrict__ row_ptr,
                                                    int* __restrict__ cursor) {
    const int T = 1024;
    int t = threadIdx.x;
    const int per = (N_NODES + T - 1) / T;
    int begin = t * per;
    int endi  = begin + per; if (endi > N_NODES) endi = N_NODES;
    int sum = 0;
    for (int i = begin; i < endi; ++i) sum += deg[i];
    __shared__ int partial[T];
    partial[t] = sum;
    __syncthreads();
    for (int off = 1; off < T; off <<= 1) {
        int v = (t >= off) ? partial[t - off] : 0;
        __syncthreads();
        partial[t] += v;
        __syncthreads();
    }
    int run = (t == 0) ? 0 : partial[t - 1];
    for (int i = begin; i < endi; ++i) {
        row_ptr[i] = run;
        cursor[i]  = run;
        run += deg[i];
    }
    if (t == T - 1) row_ptr[N_NODES] = partial[T - 1];
}

__global__ __launch_bounds__(256) void fill_kernel(const int* __restrict__ src,
                                                   const int* __restrict__ dst,
                                                   int* __restrict__ cursor,
                                                   int* __restrict__ csr_src) {
    int i = blockIdx.x * blockDim.x + threadIdx.x;
    if (i >= N_EDGES) return;
    int d = dst[i];
    int p = atomicAdd(&cursor[d], 1);
    csr_src[p] = src[i];
}

// ---------------- transpose 6 weight matrices [128x128] -> k-major ----------------
__global__ void transpose6_kernel(const float* __restrict__ w0, const float* __restrict__ w1,
                                  const float* __restrict__ w2, const float* __restrict__ w3,
                                  const float* __restrict__ w4, const float* __restrict__ w5,
                                  float* __restrict__ wt) {
    int id = blockIdx.x * blockDim.x + threadIdx.x;
    if (id >= 6 * HID * HID) return;
    int w   = id >> 14;
    int rem = id & 16383;
    int r   = rem >> 7;
    int c   = rem & 127;
    const float* src;
    switch (w) {
        case 0: src = w0; break; case 1: src = w1; break;
        case 2: src = w2; break; case 3: src = w3; break;
        case 4: src = w4; break; default: src = w5; break;
    }
    wt[(size_t)w * 16384 + c * HID + r] = src[r * HID + c];
}

// ---------------- fused SAGE layer: 64x128 tile, 128 threads, 8x8 micro-tile ----------------
// phase G: gather agg rows (CSR) into SMEM Ag[64][128]
// phase 0: acc += Ag @ WlT
// phase 1: acc += h   @ WrT  (h tile staged into front of Ag)
// epilogue: mode 0 -> C = relu(acc+bias); mode 1 -> red.add into pooled[batch[row]]
__global__ __launch_bounds__(128, 4) void sage_fused_kernel(
    const float* __restrict__ h, const int* __restrict__ row_ptr,
    const int* __restrict__ csr_src,
    const float* __restrict__ WTl, const float* __restrict__ WTr,
    const float* __restrict__ bias, float* __restrict__ C,
    const int* __restrict__ batch, float* __restrict__ pooled, int mode)
{
    __shared__ float Ag[64][128];   // 32KB; first 8KB reused as Hs[64][32] in phase 1
    __shared__ float Ws[32][128];   // 16KB  (total 48KB -> 4 blocks/SM)

    const int tid  = threadIdx.x;
    const int lane = tid & 31;
    const int warp = tid >> 5;      // 0..3
    const int cg   = tid & 15;      // cols cg*8 .. cg*8+7
    const int rg   = tid >> 4;      // rows rg*8 .. rg*8+7
    const int row0 = blockIdx.x * 64;

    // ---- phase G: gather (4 warps x 16 nodes) ----
    for (int nb = warp; nb < 64; nb += 4) {
        int node = row0 + nb;
        float4 acc = make_float4(0.f, 0.f, 0.f, 0.f);
        if (node < N_NODES) {
            int e   = __ldg(&row_ptr[node]);
            int end = __ldg(&row_ptr[node + 1]);
            for (; e + 3 < end; e += 4) {
                int s0 = __ldg(&csr_src[e]);
                int s1 = __ldg(&csr_src[e + 1]);
                int s2 = __ldg(&csr_src[e + 2]);
                int s3 = __ldg(&csr_src[e + 3]);
                float4 v0 = *reinterpret_cast<const float4*>(h + (size_t)s0 * HID + lane * 4);
                float4 v1 = *reinterpret_cast<const float4*>(h + (size_t)s1 * HID + lane * 4);
                float4 v2 = *reinterpret_cast<const float4*>(h + (size_t)s2 * HID + lane * 4);
                float4 v3 = *reinterpret_cast<const float4*>(h + (size_t)s3 * HID + lane * 4);
                acc.x += (v0.x + v1.x) + (v2.x + v3.x);
                acc.y += (v0.y + v1.y) + (v2.y + v3.y);
                acc.z += (v0.z + v1.z) + (v2.z + v3.z);
                acc.w += (v0.w + v1.w) + (v2.w + v3.w);
            }
            for (; e < end; ++e) {
                int s0 = __ldg(&csr_src[e]);
                float4 v0 = *reinterpret_cast<const float4*>(h + (size_t)s0 * HID + lane * 4);
                acc.x += v0.x; acc.y += v0.y; acc.z += v0.z; acc.w += v0.w;
            }
        }
        *reinterpret_cast<float4*>(&Ag[nb][lane * 4]) = acc;
    }

    float acc[8][8];
#pragma unroll
    for (int m = 0; m < 8; ++m)
#pragma unroll
        for (int n = 0; n < 8; ++n) acc[m][n] = 0.f;

    // ---- phase 0: acc += Ag @ WlT ----
#pragma unroll 1
    for (int kt = 0; kt < 4; ++kt) {
        const int k0 = kt * 32;
        __syncthreads();                      // prev consumers of Ws done (kt=0: gather done)
#pragma unroll
        for (int t = 0; t < 8; ++t) {         // Ws: 1024 float4, 8 per thread
            int i = tid + t * 128;
            int k = i >> 5;
            int j = i & 31;
            *reinterpret_cast<float4*>(&Ws[k][j * 4]) =
                *reinterpret_cast<const float4*>(WTl + (size_t)(k0 + k) * HID + j * 4);
        }
        __syncthreads();
#pragma unroll 4
        for (int k = 0; k < 32; ++k) {
            float4 w0 = *reinterpret_cast<float4*>(&Ws[k][cg * 8]);
            float4 w1 = *reinterpret_cast<float4*>(&Ws[k][cg * 8 + 4]);
            float a[8];
#pragma unroll
            for (int m = 0; m < 8; ++m) a[m] = Ag[rg * 8 + m][k0 + k];
#pragma unroll
            for (int m = 0; m < 8; ++m) {
                acc[m][0] += a[m] * w0.x; acc[m][1] += a[m] * w0.y;
                acc[m][2] += a[m] * w0.z; acc[m][3] += a[m] * w0.w;
                acc[m][4] += a[m] * w1.x; acc[m][5] += a[m] * w1.y;
                acc[m][6] += a[m] * w1.z; acc[m][7] += a[m] * w1.w;
            }
        }
    }

    // ---- phase 1: acc += h @ WrT (h tile staged into Hs = front of Ag) ----
    float (*Hs)[32] = reinterpret_cast<float(*)[32]>(&Ag[0][0]);
#pragma unroll 1
    for (int kt = 0; kt < 4; ++kt) {
        const int k0 = kt * 32;
        __syncthreads();                      // prev compute done (kt=0: phase-0 reads of Ag done)
#pragma unroll
        for (int t = 0; t < 4; ++t) {         // Hs: 512 float4, 4 per thread
            int i = tid + t * 128;
            int r = i >> 3;
            int q = i & 7;
            int grow = row0 + r;
            float4 v = make_float4(0.f, 0.f, 0.f, 0.f);
            if (grow < N_NODES)
                v = *reinterpret_cast<const float4*>(h + (size_t)grow * HID + k0 + q * 4);
            *reinterpret_cast<float4*>(&Hs[r][q * 4]) = v;
        }
#pragma unroll
        for (int t = 0; t < 8; ++t) {
            int i = tid + t * 128;
            int k = i >> 5;
            int j = i & 31;
            *reinterpret_cast<float4*>(&Ws[k][j * 4]) =
                *reinterpret_cast<const float4*>(WTr + (size_t)(k0 + k) * HID + j * 4);
        }
        __syncthreads();
#pragma unroll 4
        for (int k = 0; k < 32; ++k) {
            float4 w0 = *reinterpret_cast<float4*>(&Ws[k][cg * 8]);
            float4 w1 = *reinterpret_cast<float4*>(&Ws[k][cg * 8 + 4]);
            float a[8];
#pragma unroll
            for (int m = 0; m < 8; ++m) a[m] = Hs[rg * 8 + m][k];
#pragma unroll
            for (int m = 0; m < 8; ++m) {
                acc[m][0] += a[m] * w0.x; acc[m][1] += a[m] * w0.y;
                acc[m][2] += a[m] * w0.z; acc[m][3] += a[m] * w0.w;
                acc[m][4] += a[m] * w1.x; acc[m][5] += a[m] * w1.y;
                acc[m][6] += a[m] * w1.z; acc[m][7] += a[m] * w1.w;
            }
        }
    }

    // ---- epilogue ----
    const float4 bv0 = *reinterpret_cast<const float4*>(bias + cg * 8);
    const float4 bv1 = *reinterpret_cast<const float4*>(bias + cg * 8 + 4);
    if (mode == 0) {                     // write C with relu
#pragma unroll
        for (int m = 0; m < 8; ++m) {
            int grow = row0 + rg * 8 + m;
            if (grow >= N_NODES) break;
            float4 o0, o1;
            o0.x = fmaxf(acc[m][0] + bv0.x, 0.f);
            o0.y = fmaxf(acc[m][1] + bv0.y, 0.f);
            o0.z = fmaxf(acc[m][2] + bv0.z, 0.f);
            o0.w = fmaxf(acc[m][3] + bv0.w, 0.f);
            o1.x = fmaxf(acc[m][4] + bv1.x, 0.f);
            o1.y = fmaxf(acc[m][5] + bv1.y, 0.f);
            o1.z = fmaxf(acc[m][6] + bv1.z, 0.f);
            o1.w = fmaxf(acc[m][7] + bv1.w, 0.f);
            float* cp = C + (size_t)grow * HID + cg * 8;
            *reinterpret_cast<float4*>(cp)     = o0;
            *reinterpret_cast<float4*>(cp + 4) = o1;
        }
    } else {                             // pool: no relu, reduce into pooled
#pragma unroll
        for (int m = 0; m < 8; ++m) {
            int grow = row0 + rg * 8 + m;
            if (grow >= N_NODES) break;
            int g = __ldg(&batch[grow]);
            float* p = pooled + (size_t)g * HID + cg * 8;
            float o0 = acc[m][0] + bv0.x, o1 = acc[m][1] + bv0.y;
            float o2 = acc[m][2] + bv0.z, o3 = acc[m][3] + bv0.w;
            float o4 = acc[m][4] + bv1.x, o5 = acc[m][5] + bv1.y;
            float o6 = acc[m][6] + bv1.z, o7 = acc[m][7] + bv1.w;
            asm volatile("red.global.add.v4.f32 [%0], {%1, %2, %3, %4};"
                         :: "l"(p), "f"(o0), "f"(o1), "f"(o2), "f"(o3) : "memory");
            asm volatile("red.global.add.v4.f32 [%0], {%1, %2, %3, %4};"
                         :: "l"(p + 4), "f"(o4), "f"(o5), "f"(o6), "f"(o7) : "memory");
        }
    }
}

// ---------------- output head ----------------
__global__ void out_kernel(const float* __restrict__ pooled, const float* __restrict__ Wout,
                           const float* __restrict__ bout, float* __restrict__ out)
{
    int id = threadIdx.x;
    if (id >= NUM_G * 10) return;
    int g = id / 10, c = id % 10;
    float s = bout[c];
    const float* pr = pooled + g * HID;
    const float* wr = Wout + c * HID;
#pragma unroll 4
    for (int k = 0; k < HID; ++k) s += pr[k] * wr[k];
    out[id] = s;
}

// ---------------- launch ----------------
extern "C" void kernel_launch(void* const* d_in, const int* in_sizes, int n_in,
                              void* d_out, int out_size) {
    const float* x     = (const float*)d_in[0];
    const int*   ei    = (const int*)  d_in[1];
    const int*   batch = (const int*)  d_in[2];
    const float* W1l   = (const float*)d_in[3];
    const float* b1    = (const float*)d_in[4];
    const float* W1r   = (const float*)d_in[5];
    const float* W2l   = (const float*)d_in[6];
    const float* b2    = (const float*)d_in[7];
    const float* W2r   = (const float*)d_in[8];
    const float* W3l   = (const float*)d_in[9];
    const float* b3    = (const float*)d_in[10];
    const float* W3r   = (const float*)d_in[11];
    const float* Wout  = (const float*)d_in[12];
    const float* bout  = (const float*)d_in[13];
    float* out = (float*)d_out;

    const int* src = ei;
    const int* dst = ei + N_EDGES;

    float *bufA, *bufB, *wt, *pooled;
    int *deg, *rowptr, *cursor, *csrsrc;
    cudaGetSymbolAddress((void**)&bufA,   g_bufA);
    cudaGetSymbolAddress((void**)&bufB,   g_bufB);
    cudaGetSymbolAddress((void**)&wt,     g_wt);
    cudaGetSymbolAddress((void**)&pooled, g_pool);
    cudaGetSymbolAddress((void**)&deg,    g_deg);
    cudaGetSymbolAddress((void**)&rowptr, g_rowptr);
    cudaGetSymbolAddress((void**)&cursor, g_cursor);
    cudaGetSymbolAddress((void**)&csrsrc, g_csrsrc);

    const int EDGE_BLKS = (N_EDGES + 255) / 256;
    const int SAGE_BLKS = (N_NODES + 63) / 64;

    // --- CSR build (once per launch) ---
    zero_int_kernel<<<(N_NODES + 255) / 256, 256>>>(deg, N_NODES);
    hist_kernel<<<EDGE_BLKS, 256>>>(dst, deg);
    scan_kernel<<<1, 1024>>>(deg, rowptr, cursor);
    fill_kernel<<<EDGE_BLKS, 256>>>(src, dst, cursor, csrsrc);

    transpose6_kernel<<<(6 * 16384 + 255) / 256, 256>>>(W1l, W1r, W2l, W2r, W3l, W3r, wt);
    zero_kernel<<<8, 256>>>(pooled, (NUM_G * HID) / 4);

    // Layer 1: x -> bufA (relu)
    sage_fused_kernel<<<SAGE_BLKS, 128>>>(x, rowptr, csrsrc,
        wt + 0 * 16384, wt + 1 * 16384, b1, bufA, batch, pooled, 0);

    // Layer 2: bufA -> bufB (relu)
    sage_fused_kernel<<<SAGE_BLKS, 128>>>(bufA, rowptr, csrsrc,
        wt + 2 * 16384, wt + 3 * 16384, b2, bufB, batch, pooled, 0);

    // Layer 3: bufB -> pooled (no relu, fused pooling; no C write)
    sage_fused_kernel<<<SAGE_BLKS, 128>>>(bufB, rowptr, csrsrc,
        wt + 4 * 16384, wt + 5 * 16384, b3, bufA, batch, pooled, 1);

    // Head
    out_kernel<<<1, 640>>>(pooled, Wout, bout, out);
}

// round 13
// speedup vs baseline: 1.3135x; 1.3135x over previous
#include <cuda_runtime.h>
#include <cstdint>

#define N_NODES   100000
#define N_EDGES   1600000
#define HID       128
#define NUM_G     64

// ---------------- scratch (static device globals; no allocation) ----------------
__device__ float g_bufA[(size_t)N_NODES * HID];
__device__ float g_bufB[(size_t)N_NODES * HID];
__device__ float g_wt  [4 * HID * HID];        // transposed weights for layers 1-2, k-major
__device__ float g_pool[NUM_G * HID];
__device__ float g_Sagg[NUM_G * HID];          // contiguous with g_Sh not guaranteed -> zero separately
__device__ float g_Sh  [NUM_G * HID];
__device__ int   g_ng    [NUM_G];
__device__ int   g_deg   [N_NODES];
__device__ int   g_rowptr[N_NODES + 1];
__device__ int   g_cursor[N_NODES];
__device__ int   g_csrsrc[N_EDGES];

// ---------------- zero helpers ----------------
__global__ void zero_kernel(float* __restrict__ p, int n4) {
    int i = blockIdx.x * blockDim.x + threadIdx.x;
    if (i < n4) reinterpret_cast<float4*>(p)[i] = make_float4(0.f, 0.f, 0.f, 0.f);
}
__global__ void zero_int_kernel(int* __restrict__ p, int n) {
    int i = blockIdx.x * blockDim.x + threadIdx.x;
    if (i < n) p[i] = 0;
}

// ---------------- CSR build ----------------
__global__ __launch_bounds__(256) void hist_kernel(const int* __restrict__ dst, int* __restrict__ deg) {
    int i = blockIdx.x * blockDim.x + threadIdx.x;
    if (i < N_EDGES) atomicAdd(&deg[dst[i]], 1);
}

__global__ __launch_bounds__(1024) void scan_kernel(const int* __restrict__ deg,
                                                    int* __restrict__ row_ptr,
                                                    int* __restrict__ cursor) {
    const int T = 1024;
    int t = threadIdx.x;
    const int per = (N_NODES + T - 1) / T;
    int begin = t * per;
    int endi  = begin + per; if (endi > N_NODES) endi = N_NODES;
    int sum = 0;
    for (int i = begin; i < endi; ++i) sum += deg[i];
    __shared__ int partial[T];
    partial[t] = sum;
    __syncthreads();
    for (int off = 1; off < T; off <<= 1) {
        int v = (t >= off) ? partial[t - off] : 0;
        __syncthreads();
        partial[t] += v;
        __syncthreads();
    }
    int run = (t == 0) ? 0 : partial[t - 1];
    for (int i = begin; i < endi; ++i) {
        row_ptr[i] = run;
        cursor[i]  = run;
        run += deg[i];
    }
    if (t == T - 1) row_ptr[N_NODES] = partial[T - 1];
}

__global__ __launch_bounds__(256) void fill_kernel(const int* __restrict__ src,
                                                   const int* __restrict__ dst,
                                                   int* __restrict__ cursor,
                                                   int* __restrict__ csr_src) {
    int i = blockIdx.x * blockDim.x + threadIdx.x;
    if (i >= N_EDGES) return;
    int d = dst[i];
    int p = atomicAdd(&cursor[d], 1);
    csr_src[p] = src[i];
}

// ---------------- node count per graph ----------------
__global__ __launch_bounds__(256) void count_kernel(const int* __restrict__ batch, int* __restrict__ ng) {
    __shared__ int c[NUM_G];
    if (threadIdx.x < NUM_G) c[threadIdx.x] = 0;
    __syncthreads();
    int i = blockIdx.x * blockDim.x + threadIdx.x;
    if (i < N_NODES) atomicAdd(&c[batch[i]], 1);
    __syncthreads();
    if (threadIdx.x < NUM_G && c[threadIdx.x]) atomicAdd(&ng[threadIdx.x], c[threadIdx.x]);
}

// ---------------- transpose 4 weight matrices [128x128] -> k-major (layers 1-2) ----------------
__global__ void transpose4_kernel(const float* __restrict__ w0, const float* __restrict__ w1,
                                  const float* __restrict__ w2, const float* __restrict__ w3,
                                  float* __restrict__ wt) {
    int id = blockIdx.x * blockDim.x + threadIdx.x;
    if (id >= 4 * HID * HID) return;
    int w   = id >> 14;
    int rem = id & 16383;
    int r   = rem >> 7;
    int c   = rem & 127;
    const float* src;
    switch (w) {
        case 0: src = w0; break; case 1: src = w1; break;
        case 2: src = w2; break; default: src = w3; break;
    }
    wt[(size_t)w * 16384 + c * HID + r] = src[r * HID + c];
}

// ---------------- fused SAGE layer (layers 1-2): gather + GEMM + relu ----------------
__global__ __launch_bounds__(256) void sage_fused_kernel(
    const float* __restrict__ h, const int* __restrict__ row_ptr,
    const int* __restrict__ csr_src,
    const float* __restrict__ WTl, const float* __restrict__ WTr,
    const float* __restrict__ bias, float* __restrict__ C)
{
    __shared__ float Ag[64][128];   // 32KB; first 8KB reused as Hs[64][32] in phase 1
    __shared__ float Ws[32][128];   // 16KB

    const int tid  = threadIdx.x;
    const int lane = tid & 31;
    const int warp = tid >> 5;
    const int cg   = tid & 31;      // output cols cg*4..cg*4+3
    const int rg   = tid >> 5;      // output rows rg*8..rg*8+7
    const int row0 = blockIdx.x * 64;

    // ---- phase G: gather (8 warps x 8 nodes) ----
    for (int nb = warp; nb < 64; nb += 8) {
        int node = row0 + nb;
        float4 acc = make_float4(0.f, 0.f, 0.f, 0.f);
        if (node < N_NODES) {
            int e   = __ldg(&row_ptr[node]);
            int end = __ldg(&row_ptr[node + 1]);
            for (; e + 1 < end; e += 2) {
                int s0 = __ldg(&csr_src[e]);
                int s1 = __ldg(&csr_src[e + 1]);
                float4 v0 = *reinterpret_cast<const float4*>(h + (size_t)s0 * HID + lane * 4);
                float4 v1 = *reinterpret_cast<const float4*>(h + (size_t)s1 * HID + lane * 4);
                acc.x += v0.x + v1.x; acc.y += v0.y + v1.y;
                acc.z += v0.z + v1.z; acc.w += v0.w + v1.w;
            }
            if (e < end) {
                int s0 = __ldg(&csr_src[e]);
                float4 v0 = *reinterpret_cast<const float4*>(h + (size_t)s0 * HID + lane * 4);
                acc.x += v0.x; acc.y += v0.y; acc.z += v0.z; acc.w += v0.w;
            }
        }
        *reinterpret_cast<float4*>(&Ag[nb][lane * 4]) = acc;
    }
    __syncthreads();

    float acc[8][4];
#pragma unroll
    for (int m = 0; m < 8; ++m)
#pragma unroll
        for (int n = 0; n < 4; ++n) acc[m][n] = 0.f;

    // ---- phase 0: acc += Ag @ WlT ----
#pragma unroll 1
    for (int kt = 0; kt < 4; ++kt) {
        const int k0 = kt * 32;
#pragma unroll
        for (int t = 0; t < 4; ++t) {
            int i = tid + t * 256;
            int k = i >> 5;
            int j = i & 31;
            *reinterpret_cast<float4*>(&Ws[k][j * 4]) =
                *reinterpret_cast<const float4*>(WTl + (size_t)(k0 + k) * HID + j * 4);
        }
        __syncthreads();
#pragma unroll
        for (int k = 0; k < 32; ++k) {
            float4 wv = *reinterpret_cast<float4*>(&Ws[k][cg * 4]);
            float a[8];
#pragma unroll
            for (int m = 0; m < 8; ++m) a[m] = Ag[rg * 8 + m][k0 + k];
#pragma unroll
            for (int m = 0; m < 8; ++m) {
                acc[m][0] += a[m] * wv.x;
                acc[m][1] += a[m] * wv.y;
                acc[m][2] += a[m] * wv.z;
                acc[m][3] += a[m] * wv.w;
            }
        }
        __syncthreads();
    }

    // ---- phase 1: acc += h @ WrT (h tile staged into Hs = front of Ag) ----
    float (*Hs)[32] = reinterpret_cast<float(*)[32]>(&Ag[0][0]);
#pragma unroll 1
    for (int kt = 0; kt < 4; ++kt) {
        const int k0 = kt * 32;
#pragma unroll
        for (int t = 0; t < 2; ++t) {
            int i = tid + t * 256;
            int r = i >> 3;
            int q = i & 7;
            int grow = row0 + r;
            float4 v = make_float4(0.f, 0.f, 0.f, 0.f);
            if (grow < N_NODES)
                v = *reinterpret_cast<const float4*>(h + (size_t)grow * HID + k0 + q * 4);
            *reinterpret_cast<float4*>(&Hs[r][q * 4]) = v;
        }
#pragma unroll
        for (int t = 0; t < 4; ++t) {
            int i = tid + t * 256;
            int k = i >> 5;
            int j = i & 31;
            *reinterpret_cast<float4*>(&Ws[k][j * 4]) =
                *reinterpret_cast<const float4*>(WTr + (size_t)(k0 + k) * HID + j * 4);
        }
        __syncthreads();
#pragma unroll
        for (int k = 0; k < 32; ++k) {
            float4 wv = *reinterpret_cast<float4*>(&Ws[k][cg * 4]);
            float a[8];
#pragma unroll
            for (int m = 0; m < 8; ++m) a[m] = Hs[rg * 8 + m][k];
#pragma unroll
            for (int m = 0; m < 8; ++m) {
                acc[m][0] += a[m] * wv.x;
                acc[m][1] += a[m] * wv.y;
                acc[m][2] += a[m] * wv.z;
                acc[m][3] += a[m] * wv.w;
            }
        }
        __syncthreads();
    }

    // ---- epilogue: relu + store ----
    const float4 bv = *reinterpret_cast<const float4*>(bias + cg * 4);
#pragma unroll
    for (int m = 0; m < 8; ++m) {
        int grow = row0 + rg * 8 + m;
        if (grow >= N_NODES) break;
        float4 o;
        o.x = fmaxf(acc[m][0] + bv.x, 0.f);
        o.y = fmaxf(acc[m][1] + bv.y, 0.f);
        o.z = fmaxf(acc[m][2] + bv.z, 0.f);
        o.w = fmaxf(acc[m][3] + bv.w, 0.f);
        *reinterpret_cast<float4*>(C + (size_t)grow * HID + cg * 4) = o;
    }
}

// ---------------- layer-3 gather + per-graph reduction (no GEMM) ----------------
__global__ __launch_bounds__(256) void sage_pool_kernel(
    const float* __restrict__ h, const int* __restrict__ row_ptr,
    const int* __restrict__ csr_src, const int* __restrict__ batch,
    float* __restrict__ Sagg, float* __restrict__ Sh)
{
    __shared__ float Ag[64][128];   // 32KB
    __shared__ int   gb[64];

    const int tid  = threadIdx.x;
    const int lane = tid & 31;
    const int warp = tid >> 5;
    const int row0 = blockIdx.x * 64;

    // gather (8 warps x 8 nodes)
    for (int nb = warp; nb < 64; nb += 8) {
        int node = row0 + nb;
        float4 acc = make_float4(0.f, 0.f, 0.f, 0.f);
        if (node < N_NODES) {
            int e   = __ldg(&row_ptr[node]);
            int end = __ldg(&row_ptr[node + 1]);
            for (; e + 1 < end; e += 2) {
                int s0 = __ldg(&csr_src[e]);
                int s1 = __ldg(&csr_src[e + 1]);
                float4 v0 = *reinterpret_cast<const float4*>(h + (size_t)s0 * HID + lane * 4);
                float4 v1 = *reinterpret_cast<const float4*>(h + (size_t)s1 * HID + lane * 4);
                acc.x += v0.x + v1.x; acc.y += v0.y + v1.y;
                acc.z += v0.z + v1.z; acc.w += v0.w + v1.w;
            }
            if (e < end) {
                int s0 = __ldg(&csr_src[e]);
                float4 v0 = *reinterpret_cast<const float4*>(h + (size_t)s0 * HID + lane * 4);
                acc.x += v0.x; acc.y += v0.y; acc.z += v0.z; acc.w += v0.w;
            }
        }
        *reinterpret_cast<float4*>(&Ag[nb][lane * 4]) = acc;
    }
    if (tid < 64) {
        int node = row0 + tid;
        gb[tid] = (node < N_NODES) ? __ldg(&batch[node]) : -1;
    }
    __syncthreads();

    // run-wise reduce over rows (batch sorted -> few runs per block)
    // threads 0-127: reduce Ag column (tid) -> Sagg
    // threads 128-255: reduce h column (tid-128) of this block's rows -> Sh
    const int col  = tid & 127;
    const int half = tid >> 7;
    float* dstbuf = half ? Sh : Sagg;
    float acc = 0.f;
    int cur = gb[0];
#pragma unroll 4
    for (int r = 0; r < 64; ++r) {
        int g = gb[r];
        if (g != cur) {
            if (cur >= 0) atomicAdd(&dstbuf[cur * HID + col], acc);
            acc = 0.f;
            cur = g;
        }
        if (g < 0) break;
        acc += half ? __ldg(h + (size_t)(row0 + r) * HID + col) : Ag[r][col];
    }
    if (cur >= 0) atomicAdd(&dstbuf[cur * HID + col], acc);
}

// ---------------- tiny pooled GEMM ----------------
__global__ __launch_bounds__(256) void pooled_kernel(
    const float* __restrict__ Sagg, const float* __restrict__ Sh,
    const float* __restrict__ W3l, const float* __restrict__ W3r,
    const float* __restrict__ b3, const int* __restrict__ ng,
    float* __restrict__ pooled)
{
    int id = blockIdx.x * blockDim.x + threadIdx.x;   // 64*128 = 8192
    if (id >= NUM_G * HID) return;
    int g = id >> 7;
    int c = id & 127;
    const float* sa = Sagg + g * HID;
    const float* sh = Sh   + g * HID;
    const float* wl = W3l + c * HID;
    const float* wr = W3r + c * HID;
    float s = (float)ng[g] * b3[c];
#pragma unroll 4
    for (int k = 0; k < HID; ++k) s += sa[k] * wl[k] + sh[k] * wr[k];
    pooled[id] = s;
}

// ---------------- output head ----------------
__global__ void out_kernel(const float* __restrict__ pooled, const float* __restrict__ Wout,
                           const float* __restrict__ bout, float* __restrict__ out)
{
    int id = threadIdx.x;
    if (id >= NUM_G * 10) return;
    int g = id / 10, c = id % 10;
    float s = bout[c];
    const float* pr = pooled + g * HID;
    const float* wr = Wout + c * HID;
#pragma unroll 4
    for (int k = 0; k < HID; ++k) s += pr[k] * wr[k];
    out[id] = s;
}

// ---------------- launch ----------------
extern "C" void kernel_launch(void* const* d_in, const int* in_sizes, int n_in,
                              void* d_out, int out_size) {
    const float* x     = (const float*)d_in[0];
    const int*   ei    = (const int*)  d_in[1];
    const int*   batch = (const int*)  d_in[2];
    const float* W1l   = (const float*)d_in[3];
    const float* b1    = (const float*)d_in[4];
    const float* W1r   = (const float*)d_in[5];
    const float* W2l   = (const float*)d_in[6];
    const float* b2    = (const float*)d_in[7];
    const float* W2r   = (const float*)d_in[8];
    const float* W3l   = (const float*)d_in[9];
    const float* b3    = (const float*)d_in[10];
    const float* W3r   = (const float*)d_in[11];
    const float* Wout  = (const float*)d_in[12];
    const float* bout  = (const float*)d_in[13];
    float* out = (float*)d_out;

    const int* src = ei;
    const int* dst = ei + N_EDGES;

    float *bufA, *bufB, *wt, *pooled, *Sagg, *Sh;
    int *deg, *rowptr, *cursor, *csrsrc, *ng;
    cudaGetSymbolAddress((void**)&bufA,   g_bufA);
    cudaGetSymbolAddress((void**)&bufB,   g_bufB);
    cudaGetSymbolAddress((void**)&wt,     g_wt);
    cudaGetSymbolAddress((void**)&pooled, g_pool);
    cudaGetSymbolAddress((void**)&Sagg,   g_Sagg);
    cudaGetSymbolAddress((void**)&Sh,     g_Sh);
    cudaGetSymbolAddress((void**)&ng,     g_ng);
    cudaGetSymbolAddress((void**)&deg,    g_deg);
    cudaGetSymbolAddress((void**)&rowptr, g_rowptr);
    cudaGetSymbolAddress((void**)&cursor, g_cursor);
    cudaGetSymbolAddress((void**)&csrsrc, g_csrsrc);

    const int EDGE_BLKS = (N_EDGES + 255) / 256;
    const int SAGE_BLKS = (N_NODES + 63) / 64;
    const int GH4       = (NUM_G * HID) / 4;          // 2048 float4 per buffer

    // --- CSR build (once per launch) ---
    zero_int_kernel<<<(N_NODES + 255) / 256, 256>>>(deg, N_NODES);
    hist_kernel<<<EDGE_BLKS, 256>>>(dst, deg);
    scan_kernel<<<1, 1024>>>(deg, rowptr, cursor);
    fill_kernel<<<EDGE_BLKS, 256>>>(src, dst, cursor, csrsrc);

    transpose4_kernel<<<(4 * 16384 + 255) / 256, 256>>>(W1l, W1r, W2l, W2r, wt);
    zero_int_kernel<<<1, NUM_G>>>(ng, NUM_G);
    count_kernel<<<(N_NODES + 255) / 256, 256>>>(batch, ng);
    // FULLY zero the per-launch accumulators (bug in R12: only 512/2048 float4 were zeroed)
    zero_kernel<<<(GH4 + 255) / 256, 256>>>(Sagg, GH4);   // 8 blocks
    zero_kernel<<<(GH4 + 255) / 256, 256>>>(Sh,   GH4);   // 8 blocks

    // Layer 1: x -> bufA (relu)
    sage_fused_kernel<<<SAGE_BLKS, 256>>>(x, rowptr, csrsrc,
        wt + 0 * 16384, wt + 1 * 16384, b1, bufA);

    // Layer 2: bufA -> bufB (relu)
    sage_fused_kernel<<<SAGE_BLKS, 256>>>(bufA, rowptr, csrsrc,
        wt + 2 * 16384, wt + 3 * 16384, b2, bufB);

    // Layer 3: gather + per-graph reduce only (GEMM commuted past the pooling sum)
    sage_pool_kernel<<<SAGE_BLKS, 256>>>(bufB, rowptr, csrsrc, batch, Sagg, Sh);

    // pooled = Sagg@W3l^T + Sh@W3r^T + ng*b3 ; out = pooled@Wout^T + bout
    pooled_kernel<<<(NUM_G * HID + 255) / 256, 256>>>(Sagg, Sh, W3l, W3r, b3, ng, pooled);
    out_kernel<<<1, 640>>>(pooled, Wout, bout, out);
}